// round 9
// baseline (speedup 1.0000x reference)
#include <cuda_runtime.h>

// ---------------------------------------------------------------------------
// TwoBodySphericalHarmonicTensorEmbed
//   out[e, c, j] = sh_j(edge_vec[e]) * w[e, c, widx[j]]
//   w[e, c, i]   = dot(edge_invariants[e, :64], W_lin[:, 3c+i])
//   widx = {0,1,1,1,2,2,2,2,2}
// Fused persistent kernel: W in smem, f32x2-packed GEMM, smem-staged
// epilogue with 16B streaming stores.
// ---------------------------------------------------------------------------

#define NTHREADS 256
#define E_TILE   32

// smem layout (in floats)
#define W_SZ     (64 * 192)            // 12288
#define A_OFF    (W_SZ)                // A_t: [k=64][e=32], XOR-swizzled
#define A_SZ     (64 * 32)             // 2048
#define WS_OFF   (A_OFF + A_SZ)        // w_s: [n=192][e], stride 33
#define WS_STR   33
#define WS_SZ    (192 * WS_STR)        // 6336
#define SH_OFF   (WS_OFF + WS_SZ)      // sh_s: [e=32][9]
#define SH_SZ    (32 * 9)              // 288
#define SMEM_FLOATS (SH_OFF + SH_SZ)   // 20960 floats = 83840 B

__device__ __forceinline__ unsigned long long pack2(float lo, float hi) {
    unsigned long long r;
    asm("mov.b64 %0, {%1, %2};" : "=l"(r) : "f"(lo), "f"(hi));
    return r;
}
__device__ __forceinline__ void fma2(unsigned long long& d,
                                     unsigned long long a,
                                     unsigned long long b) {
    asm("fma.rn.f32x2 %0, %1, %2, %0;" : "+l"(d) : "l"(a), "l"(b));
}
__device__ __forceinline__ void unpack2(unsigned long long v, float& lo, float& hi) {
    asm("mov.b64 {%0, %1}, %2;" : "=f"(lo), "=f"(hi) : "l"(v));
}

__global__ void __launch_bounds__(NTHREADS, 2)
embed_kernel(const float* __restrict__ edge_vec,
             const float* __restrict__ EI,       // [E, 64]
             const float* __restrict__ Wg,       // [64, 192]
             float* __restrict__ out,            // [E, 64, 9]
             int E, int ntiles)
{
    extern __shared__ float smem[];
    float* W_s  = smem;
    float* A_t  = smem + A_OFF;
    float* w_s  = smem + WS_OFF;
    float* sh_s = smem + SH_OFF;

    const int tid = threadIdx.x;

    // ---- stage W_lin once per block (persistent grid) ----
    {
        const float4* wg4 = reinterpret_cast<const float4*>(Wg);
        float4* ws4 = reinterpret_cast<float4*>(W_s);
        #pragma unroll
        for (int i = 0; i < 12; i++)
            ws4[tid + i * NTHREADS] = wg4[tid + i * NTHREADS];
    }

    // GEMM thread mapping: warp-uniform edge group, 32 channels per warp
    const int c  = tid & 63;       // output channel 0..63
    const int eg = tid >> 6;       // edge group 0..3 (8 edges each)
    const int e0 = eg * 8;

    // epilogue thread mapping
    const int ep_e  = tid >> 3;    // edge within tile 0..31
    const int ep_cg = tid & 7;     // channel group (8 channels each)

    for (int tile = blockIdx.x; tile < ntiles; tile += gridDim.x) {
        const int ebase = tile * E_TILE;

        __syncthreads();  // previous tile's epilogue done reading smem

        // ---- stage A tile, transposed + XOR-swizzled: A_t[k][e ^ sw(k)] ----
        #pragma unroll
        for (int iter = 0; iter < 2; iter++) {
            const int f  = iter * NTHREADS + tid;   // 0..511
            const int e  = f >> 4;                  // 0..31
            const int kq = f & 15;                  // float4 index along k
            const int eglob = ebase + e;
            float4 v = make_float4(0.f, 0.f, 0.f, 0.f);
            if (eglob < E)
                v = *reinterpret_cast<const float4*>(EI + (size_t)eglob * 64 + kq * 4);
            const float vv[4] = {v.x, v.y, v.z, v.w};
            #pragma unroll
            for (int i = 0; i < 4; i++) {
                const int k  = kq * 4 + i;
                const int sw = ((k & 7) ^ ((k >> 3) & 7)) << 2;
                A_t[k * 32 + (e ^ sw)] = vv[i];
            }
        }

        // ---- spherical harmonics for the 32 edges ----
        if (tid < 32) {
            const int eglob = ebase + tid;
            float s[9] = {0.f, 0.f, 0.f, 0.f, 0.f, 0.f, 0.f, 0.f, 0.f};
            if (eglob < E) {
                const float vx = edge_vec[(size_t)eglob * 3 + 0];
                const float vy = edge_vec[(size_t)eglob * 3 + 1];
                const float vz = edge_vec[(size_t)eglob * 3 + 2];
                const float inv = rsqrtf(vx * vx + vy * vy + vz * vz);
                const float x = vx * inv, y = vy * inv, z = vz * inv;
                const float SQ3  = 1.7320508075688772f;
                const float SQ5  = 2.2360679774997896f;
                const float SQ15 = 3.8729833462074170f;
                s[0] = 1.0f;
                s[1] = SQ3 * x;
                s[2] = SQ3 * y;
                s[3] = SQ3 * z;
                s[4] = SQ15 * x * z;
                s[5] = SQ15 * x * y;
                s[6] = SQ5 * (y * y - 0.5f * (x * x + z * z));
                s[7] = SQ15 * y * z;
                s[8] = (SQ15 * 0.5f) * (z * z - x * x);
            }
            #pragma unroll
            for (int j = 0; j < 9; j++) sh_s[tid * 9 + j] = s[j];
        }

        __syncthreads();

        // ---- GEMM: acc[ir][p] = f32x2 over edge pairs (e0+2p, e0+2p+1) ----
        unsigned long long acc[3][4];
        #pragma unroll
        for (int ir = 0; ir < 3; ir++)
            #pragma unroll
            for (int p = 0; p < 4; p++) acc[ir][p] = 0ull;

        #pragma unroll
        for (int k = 0; k < 64; k++) {
            const int sw = ((k & 7) ^ ((k >> 3) & 7)) << 2;
            const ulonglong2 a01 =
                *reinterpret_cast<const ulonglong2*>(A_t + k * 32 + (e0 ^ sw));
            const ulonglong2 a23 =
                *reinterpret_cast<const ulonglong2*>(A_t + k * 32 + ((e0 + 4) ^ sw));
            const float* wr = W_s + k * 192 + 3 * c;
            const unsigned long long pw0 = pack2(wr[0], wr[0]);
            const unsigned long long pw1 = pack2(wr[1], wr[1]);
            const unsigned long long pw2 = pack2(wr[2], wr[2]);
            fma2(acc[0][0], a01.x, pw0); fma2(acc[0][1], a01.y, pw0);
            fma2(acc[0][2], a23.x, pw0); fma2(acc[0][3], a23.y, pw0);
            fma2(acc[1][0], a01.x, pw1); fma2(acc[1][1], a01.y, pw1);
            fma2(acc[1][2], a23.x, pw1); fma2(acc[1][3], a23.y, pw1);
            fma2(acc[2][0], a01.x, pw2); fma2(acc[2][1], a01.y, pw2);
            fma2(acc[2][2], a23.x, pw2); fma2(acc[2][3], a23.y, pw2);
        }

        // ---- write w to smem: w_s[n][e], n = 3c+ir ----
        #pragma unroll
        for (int ir = 0; ir < 3; ir++) {
            float* base = w_s + (3 * c + ir) * WS_STR + e0;
            #pragma unroll
            for (int p = 0; p < 4; p++) {
                float lo, hi;
                unpack2(acc[ir][p], lo, hi);
                base[2 * p]     = lo;
                base[2 * p + 1] = hi;
            }
        }

        __syncthreads();

        // ---- epilogue: thread = (edge, 8-channel group), 18x float4 stores ----
        const int eglob = ebase + ep_e;
        if (eglob < E) {
            float sh9[9];
            #pragma unroll
            for (int j = 0; j < 9; j++) sh9[j] = sh_s[ep_e * 9 + j];

            float wv[24];  // 8 channels x 3 irreps
            #pragma unroll
            for (int m = 0; m < 24; m++)
                wv[m] = w_s[(ep_cg * 24 + m) * WS_STR + ep_e];

            const int WIDX[9] = {0, 1, 1, 1, 2, 2, 2, 2, 2};
            float4* ob = reinterpret_cast<float4*>(
                out + (size_t)eglob * 576 + ep_cg * 72);

            #pragma unroll
            for (int f = 0; f < 18; f++) {
                float t[4];
                #pragma unroll
                for (int q = 0; q < 4; q++) {
                    const int idx = 4 * f + q;     // 0..71
                    const int u = idx / 9;         // compile-time after unroll
                    const int j = idx % 9;
                    t[q] = sh9[j] * wv[3 * u + WIDX[j]];
                }
                float4 v;
                v.x = t[0]; v.y = t[1]; v.z = t[2]; v.w = t[3];
                __stcs(ob + f, v);  // streaming: output never re-read
            }
        }
    }
}

extern "C" void kernel_launch(void* const* d_in, const int* in_sizes, int n_in,
                              void* d_out, int out_size)
{
    const float* edge_vec = (const float*)d_in[0];
    const float* EI       = (const float*)d_in[1];
    const float* Wg       = (const float*)d_in[2];
    float* out            = (float*)d_out;

    const int E      = in_sizes[0] / 3;
    const int ntiles = (E + E_TILE - 1) / E_TILE;

    const int smem_bytes = SMEM_FLOATS * sizeof(float);  // 83840 B
    cudaFuncSetAttribute(embed_kernel,
                         cudaFuncAttributeMaxDynamicSharedMemorySize,
                         smem_bytes);

    int grid = 304;  // 2 CTAs/SM on 152-SM GB300 (persistent)
    if (grid > ntiles) grid = ntiles;

    embed_kernel<<<grid, NTHREADS, smem_bytes>>>(edge_vec, EI, Wg, out, E, ntiles);
}